// round 10
// baseline (speedup 1.0000x reference)
#include <cuda_runtime.h>
#include <cuda_fp16.h>
#include <cstdint>

// GraphConv: out = relu( segment_sum(feature[src] -> dst) @ W^T + b )
// R10: R9 + ldmatrix.x4 fragment loads in the fp16 HMMA GEMM.

constexpr int N_NODES = 50000;
constexpr int N_EDGES = 800000;
constexpr int D       = 128;
constexpr int CAP     = 128;

// ---- static scratch ----
__device__ __half g_feat16[N_NODES * D];     // 12.8 MB fp16 feature cache
__device__ __half g_agg16[N_NODES * D];      // 12.8 MB fp16 aggregated features
__device__ int    g_bins[N_NODES * CAP];     // 25.6 MB binned src ids
__device__ int    g_cursor[N_NODES];         // fill cursor == in-degree
__device__ int    g_ovf_cnt;
__device__ int2   g_ovf[N_EDGES];            // overflow edges (correctness net)

// ---------------------------------------------------------------------------
// 1) prep: convert feature -> fp16, zero cursors + overflow counter
// ---------------------------------------------------------------------------
__global__ void __launch_bounds__(256) prep_kernel(const float4* __restrict__ feat)
{
    int i = blockIdx.x * blockDim.x + threadIdx.x;
    if (i < N_NODES * D / 8) {
        float4 a = feat[i * 2];
        float4 b = feat[i * 2 + 1];
        __half2 h0 = __floats2half2_rn(a.x, a.y);
        __half2 h1 = __floats2half2_rn(a.z, a.w);
        __half2 h2 = __floats2half2_rn(b.x, b.y);
        __half2 h3 = __floats2half2_rn(b.z, b.w);
        uint4 v;
        v.x = *reinterpret_cast<uint32_t*>(&h0);
        v.y = *reinterpret_cast<uint32_t*>(&h1);
        v.z = *reinterpret_cast<uint32_t*>(&h2);
        v.w = *reinterpret_cast<uint32_t*>(&h3);
        reinterpret_cast<uint4*>(g_feat16)[i] = v;
    }
    if (i < N_NODES) g_cursor[i] = 0;
    if (i == 0) g_ovf_cnt = 0;
}

// ---------------------------------------------------------------------------
// 2) bin fill: 4 edges per thread, independent atomic chains (MLP=4)
// ---------------------------------------------------------------------------
__device__ __forceinline__ void fill_one(int src, int dst, int pos) {
    if (pos < CAP) {
        g_bins[dst * CAP + pos] = src;
    } else {
        int o = atomicAdd(&g_ovf_cnt, 1);
        g_ovf[o] = make_int2(src, dst);
    }
}

__global__ void __launch_bounds__(256) fill_kernel(const int* __restrict__ ei)
{
    int i = blockIdx.x * blockDim.x + threadIdx.x;   // 0 .. N_EDGES/4-1
    if (i >= N_EDGES / 4) return;
    int4 s = reinterpret_cast<const int4*>(ei)[i];
    int4 d = reinterpret_cast<const int4*>(ei + N_EDGES)[i];
    int p0 = atomicAdd(&g_cursor[d.x], 1);
    int p1 = atomicAdd(&g_cursor[d.y], 1);
    int p2 = atomicAdd(&g_cursor[d.z], 1);
    int p3 = atomicAdd(&g_cursor[d.w], 1);
    fill_one(s.x, d.x, p0);
    fill_one(s.y, d.y, p1);
    fill_one(s.z, d.z, p2);
    fill_one(s.w, d.w, p3);
}

// ---------------------------------------------------------------------------
// 3) gather: warp-per-node, lane owns 4 halfs (uint2), fp32 accum, unroll 8.
// ---------------------------------------------------------------------------
__device__ __forceinline__ void acc_add(float4& a, uint2 u) {
    __half2 h0 = *reinterpret_cast<__half2*>(&u.x);
    __half2 h1 = *reinterpret_cast<__half2*>(&u.y);
    float2 f0 = __half22float2(h0);
    float2 f1 = __half22float2(h1);
    a.x += f0.x; a.y += f0.y; a.z += f1.x; a.w += f1.y;
}

__global__ void __launch_bounds__(256) gather_kernel()
{
    int warp = (blockIdx.x * blockDim.x + threadIdx.x) >> 5;
    int lane = threadIdx.x & 31;
    if (warp >= N_NODES) return;

    const uint2* f = reinterpret_cast<const uint2*>(g_feat16);  // 32 uint2/row

    int degf = g_cursor[warp];
    int deg  = min(degf, CAP);
    const int* bin = &g_bins[warp * CAP];

    float4 acc = make_float4(0.f, 0.f, 0.f, 0.f);

    int e = 0;
    for (; e + 8 <= deg; e += 8) {
        int s0 = bin[e];     int s1 = bin[e + 1];
        int s2 = bin[e + 2]; int s3 = bin[e + 3];
        int s4 = bin[e + 4]; int s5 = bin[e + 5];
        int s6 = bin[e + 6]; int s7 = bin[e + 7];
        uint2 u0 = f[s0 * 32 + lane];
        uint2 u1 = f[s1 * 32 + lane];
        uint2 u2 = f[s2 * 32 + lane];
        uint2 u3 = f[s3 * 32 + lane];
        uint2 u4 = f[s4 * 32 + lane];
        uint2 u5 = f[s5 * 32 + lane];
        uint2 u6 = f[s6 * 32 + lane];
        uint2 u7 = f[s7 * 32 + lane];
        acc_add(acc, u0); acc_add(acc, u1);
        acc_add(acc, u2); acc_add(acc, u3);
        acc_add(acc, u4); acc_add(acc, u5);
        acc_add(acc, u6); acc_add(acc, u7);
    }
    for (; e + 4 <= deg; e += 4) {
        int s0 = bin[e];     int s1 = bin[e + 1];
        int s2 = bin[e + 2]; int s3 = bin[e + 3];
        uint2 u0 = f[s0 * 32 + lane];
        uint2 u1 = f[s1 * 32 + lane];
        uint2 u2 = f[s2 * 32 + lane];
        uint2 u3 = f[s3 * 32 + lane];
        acc_add(acc, u0); acc_add(acc, u1);
        acc_add(acc, u2); acc_add(acc, u3);
    }
    for (; e < deg; e++) {
        uint2 u = f[bin[e] * 32 + lane];
        acc_add(acc, u);
    }

    if (degf > CAP) {                 // inline overflow fixup (expected never)
        int cnt = g_ovf_cnt;
        for (int j = 0; j < cnt; j++) {
            int2 sd = g_ovf[j];
            if (sd.y == warp) {
                uint2 u = f[sd.x * 32 + lane];
                acc_add(acc, u);
            }
        }
    }

    __half2 h0 = __floats2half2_rn(acc.x, acc.y);
    __half2 h1 = __floats2half2_rn(acc.z, acc.w);
    uint2 st;
    st.x = *reinterpret_cast<uint32_t*>(&h0);
    st.y = *reinterpret_cast<uint32_t*>(&h1);
    reinterpret_cast<uint2*>(g_agg16)[warp * 32 + lane] = st;
}

// ---------------------------------------------------------------------------
// 4) GEMM via fp16 mma m16n8k16 + ldmatrix.x4: out = relu( agg16 @ W^T + b )
//    Block: 128 rows x 128 cols, 256 threads (8 warps).
//    Full-K smem tiles: As[128][136] half, Bs[128][136] half (69.6 KB dynamic).
//    Row stride 136 halfs = 272 B => 4-bank rotation per row: each 8-address
//    ldmatrix group covers all 32 banks once (conflict-free).
// ---------------------------------------------------------------------------
constexpr int GM    = 128;
constexpr int ASTR  = 136;                       // half stride per row
constexpr int SMEM_BYTES = 2 * GM * ASTR * 2;    // 69632

__device__ __forceinline__ void mma_f16(
    float& d0, float& d1, float& d2, float& d3,
    uint32_t a0, uint32_t a1, uint32_t a2, uint32_t a3,
    uint32_t b0, uint32_t b1)
{
    asm volatile(
        "mma.sync.aligned.m16n8k16.row.col.f32.f16.f16.f32 "
        "{%0,%1,%2,%3}, {%4,%5,%6,%7}, {%8,%9}, {%0,%1,%2,%3};"
        : "+f"(d0), "+f"(d1), "+f"(d2), "+f"(d3)
        : "r"(a0), "r"(a1), "r"(a2), "r"(a3), "r"(b0), "r"(b1));
}

__device__ __forceinline__ void ldsm_x4(
    uint32_t& r0, uint32_t& r1, uint32_t& r2, uint32_t& r3, uint32_t addr)
{
    asm volatile(
        "ldmatrix.sync.aligned.m8n8.x4.shared.b16 {%0,%1,%2,%3}, [%4];"
        : "=r"(r0), "=r"(r1), "=r"(r2), "=r"(r3) : "r"(addr));
}

__global__ void __launch_bounds__(256) gemm_f16_bias_relu_kernel(
    const float* __restrict__ Wm, const float* __restrict__ bias,
    float* __restrict__ out)
{
    extern __shared__ __half sm[];
    __half* As = sm;               // [128][136]
    __half* Bs = sm + GM * ASTR;   // [128][136]

    const int t    = threadIdx.x;
    const int lane = t & 31;
    const int w    = t >> 5;
    const int m0   = blockIdx.x * GM;
    const int gp   = lane >> 2;
    const int tg   = lane & 3;

    // ---- stage A (fp16 copy): 128 rows x 16 uint4 = 2048 / 256 thr = 8 each ----
#pragma unroll
    for (int i = 0; i < 8; i++) {
        int lin = t + i * 256;          // 0..2047
        int row = lin >> 4;             // 0..127
        int q   = lin & 15;             // uint4 (8 halfs) within row
        int m   = m0 + row;
        uint4 v = make_uint4(0u, 0u, 0u, 0u);
        if (m < N_NODES)
            v = reinterpret_cast<const uint4*>(g_agg16 + m * D)[q];
        *reinterpret_cast<uint4*>(&As[row * ASTR + q * 8]) = v;
    }
    // ---- stage W (fp32 -> fp16): thread handles half a row (64 floats) ----
    {
        int n    = t >> 1;              // 0..127
        int half = t & 1;               // which 64-float half
        const float4* wr = reinterpret_cast<const float4*>(Wm + n * D + half * 64);
#pragma unroll
        for (int q = 0; q < 16; q++) {
            float4 v = wr[q];
            __half2 h0 = __floats2half2_rn(v.x, v.y);
            __half2 h1 = __floats2half2_rn(v.z, v.w);
            uint2 u;
            u.x = *reinterpret_cast<uint32_t*>(&h0);
            u.y = *reinterpret_cast<uint32_t*>(&h1);
            *reinterpret_cast<uint2*>(&Bs[n * ASTR + half * 64 + q * 4]) = u;
        }
    }
    __syncthreads();

    float acc[16][4];
#pragma unroll
    for (int nt = 0; nt < 16; nt++)
#pragma unroll
        for (int j = 0; j < 4; j++) acc[nt][j] = 0.f;

    // ---- ldmatrix addressing ----
    const uint32_t as_s = (uint32_t)__cvta_generic_to_shared(As);
    const uint32_t bs_s = (uint32_t)__cvta_generic_to_shared(Bs);
    const int tq = lane >> 3;           // tile index 0..3
    const int rl = lane & 7;            // row within tile
    // A tiles: t0=(m0..8,k0..8) t1=(m8..16,k0..8) t2=(m0..8,k8..16) t3=(m8..16,k8..16)
    const uint32_t a_row  = (uint32_t)(w * 16 + ((tq & 1) << 3) + rl);
    const uint32_t a_koff = (uint32_t)((tq >> 1) << 3);
    const uint32_t a_base = as_s + (a_row * ASTR + a_koff) * 2;
    // B tiles for pair p: t0=(n p*16.., k0) t1=(n p*16.., k8) t2=(n p*16+8.., k0) t3=(.. k8)
    const uint32_t b_rowoff = (uint32_t)(((tq >> 1) << 3) + rl);
    const uint32_t b_koff   = (uint32_t)((tq & 1) << 3);

#pragma unroll
    for (int ks = 0; ks < 8; ks++) {
        int kb = ks * 16;
        uint32_t a0, a1, a2, a3;
        ldsm_x4(a0, a1, a2, a3, a_base + kb * 2);
#pragma unroll
        for (int p = 0; p < 8; p++) {
            uint32_t baddr = bs_s +
                (((uint32_t)(p * 16) + b_rowoff) * ASTR + b_koff + kb) * 2;
            uint32_t b0, b1, b2, b3;
            ldsm_x4(b0, b1, b2, b3, baddr);
            mma_f16(acc[2 * p][0], acc[2 * p][1], acc[2 * p][2], acc[2 * p][3],
                    a0, a1, a2, a3, b0, b1);
            mma_f16(acc[2 * p + 1][0], acc[2 * p + 1][1],
                    acc[2 * p + 1][2], acc[2 * p + 1][3],
                    a0, a1, a2, a3, b2, b3);
        }
    }

    // ---- epilogue: + bias, relu, store ----
    int r0 = m0 + w * 16 + gp;
#pragma unroll
    for (int nt = 0; nt < 16; nt++) {
        int c = nt * 8 + tg * 2;
        float b0 = __ldg(&bias[c]);
        float b1 = __ldg(&bias[c + 1]);
        if (r0 < N_NODES) {
            float2 v;
            v.x = fmaxf(acc[nt][0] + b0, 0.f);
            v.y = fmaxf(acc[nt][1] + b1, 0.f);
            *reinterpret_cast<float2*>(out + r0 * D + c) = v;
        }
        if (r0 + 8 < N_NODES) {
            float2 v;
            v.x = fmaxf(acc[nt][2] + b0, 0.f);
            v.y = fmaxf(acc[nt][3] + b1, 0.f);
            *reinterpret_cast<float2*>(out + (r0 + 8) * D + c) = v;
        }
    }
}

// ---------------------------------------------------------------------------
extern "C" void kernel_launch(void* const* d_in, const int* in_sizes, int n_in,
                              void* d_out, int out_size)
{
    const float* feature = (const float*)d_in[0];   // [50000,128]
    const float* Wm      = (const float*)d_in[1];   // [128,128]
    const float* bias    = (const float*)d_in[2];   // [128]
    const int*   ei      = (const int*)  d_in[3];   // [2,800000]
    float*       out     = (float*)d_out;           // [50000,128]

    (void)in_sizes; (void)n_in; (void)out_size;

    cudaFuncSetAttribute(gemm_f16_bias_relu_kernel,
                         cudaFuncAttributeMaxDynamicSharedMemorySize, SMEM_BYTES);

    prep_kernel<<<(N_NODES * D / 8 + 255) / 256, 256>>>(
        reinterpret_cast<const float4*>(feature));
    fill_kernel<<<(N_EDGES / 4 + 255) / 256, 256>>>(ei);
    {
        int total_threads = N_NODES * 32;
        gather_kernel<<<(total_threads + 255) / 256, 256>>>();
    }
    {
        int blocks = (N_NODES + GM - 1) / GM;   // 391
        gemm_f16_bias_relu_kernel<<<blocks, 256, SMEM_BYTES>>>(Wm, bias, out);
    }
}

// round 12
// speedup vs baseline: 1.2331x; 1.2331x over previous
#include <cuda_runtime.h>
#include <cuda_fp16.h>
#include <cstdint>

// GraphConv: out = relu( segment_sum(feature[src] -> dst) @ W^T + b )
// R12 (= R11 resubmit; infra flake): h = fp16(feature @ W^T) FIRST (smem-free
// HMMA), then atomic-free gather of h with fused bias+relu epilogue.
//   1) prep: build fragment-major fp16 W table, zero cursors
//   2) fill: capacity-binned CSR (4 edges/thread)
//   3) gemm: warp-per-16-rows, direct-LDG fragments, no smem/sync
//   4) gather: warp-per-node over h16, + bias, relu, write out

constexpr int N_NODES = 50000;
constexpr int N_EDGES = 800000;
constexpr int D       = 128;
constexpr int CAP     = 128;

// ---- static scratch ----
__device__ __half g_h16[N_NODES * D];        // 12.8 MB h = fp16(feature @ W^T)
__device__ uint4  g_wfrag[8 * 8 * 32];       // 32 KB fragment-major fp16 W
__device__ int    g_bins[N_NODES * CAP];     // 25.6 MB binned src ids
__device__ int    g_cursor[N_NODES];         // fill cursor == in-degree
__device__ int    g_ovf_cnt;
__device__ int2   g_ovf[N_EDGES];            // overflow edges (correctness net)

// ---------------------------------------------------------------------------
// 1) prep: build g_wfrag + zero cursors.
//    g_wfrag[ks*256 + np*32 + lane] = uint4 {
//      x: half2( W[16np+gp  ][16ks+2tg  ], W[16np+gp  ][16ks+2tg+1] )
//      y: half2( W[16np+gp  ][16ks+2tg+8], W[16np+gp  ][16ks+2tg+9] )
//      z: half2( W[16np+8+gp][16ks+2tg  ], W[16np+8+gp][16ks+2tg+1] )
//      w: half2( W[16np+8+gp][16ks+2tg+8], W[16np+8+gp][16ks+2tg+9] )
//    }   (gp = lane>>2, tg = lane&3) — matches R9-validated mma B mapping.
// ---------------------------------------------------------------------------
__device__ __forceinline__ uint32_t pack_h2(float a, float b) {
    __half2 h = __floats2half2_rn(a, b);
    return *reinterpret_cast<uint32_t*>(&h);
}

__global__ void __launch_bounds__(256) prep_kernel(const float* __restrict__ Wm)
{
    int i = blockIdx.x * blockDim.x + threadIdx.x;
    if (i < 2048) {
        int ks   = i >> 8;
        int np   = (i >> 5) & 7;
        int lane = i & 31;
        int gp   = lane >> 2;
        int tg   = lane & 3;
        int k0   = 16 * ks + 2 * tg;
        int n0   = 16 * np + gp;
        uint4 v;
        v.x = pack_h2(Wm[n0 * D + k0    ], Wm[n0 * D + k0 + 1]);
        v.y = pack_h2(Wm[n0 * D + k0 + 8], Wm[n0 * D + k0 + 9]);
        v.z = pack_h2(Wm[(n0 + 8) * D + k0    ], Wm[(n0 + 8) * D + k0 + 1]);
        v.w = pack_h2(Wm[(n0 + 8) * D + k0 + 8], Wm[(n0 + 8) * D + k0 + 9]);
        g_wfrag[i] = v;
    }
    if (i < N_NODES) g_cursor[i] = 0;
    if (i == 0) g_ovf_cnt = 0;
}

// ---------------------------------------------------------------------------
// 2) bin fill: 4 edges per thread (MLP=4)
// ---------------------------------------------------------------------------
__device__ __forceinline__ void fill_one(int src, int dst, int pos) {
    if (pos < CAP) {
        g_bins[dst * CAP + pos] = src;
    } else {
        int o = atomicAdd(&g_ovf_cnt, 1);
        g_ovf[o] = make_int2(src, dst);
    }
}

__global__ void __launch_bounds__(256) fill_kernel(const int* __restrict__ ei)
{
    int i = blockIdx.x * blockDim.x + threadIdx.x;
    if (i >= N_EDGES / 4) return;
    int4 s = reinterpret_cast<const int4*>(ei)[i];
    int4 d = reinterpret_cast<const int4*>(ei + N_EDGES)[i];
    int p0 = atomicAdd(&g_cursor[d.x], 1);
    int p1 = atomicAdd(&g_cursor[d.y], 1);
    int p2 = atomicAdd(&g_cursor[d.z], 1);
    int p3 = atomicAdd(&g_cursor[d.w], 1);
    fill_one(s.x, d.x, p0);
    fill_one(s.y, d.y, p1);
    fill_one(s.z, d.z, p2);
    fill_one(s.w, d.w, p3);
}

// ---------------------------------------------------------------------------
// 3) gemm: h16 = fp16( feature @ W^T ).  No smem, no syncs.
//    One warp per 16 rows (3125 warps). A fragments: direct coalesced float2
//    loads + cvt. B fragments: one uint4 LDG per 2 n-tiles from g_wfrag (L1-hot).
// ---------------------------------------------------------------------------
__device__ __forceinline__ void mma_f16(
    float& d0, float& d1, float& d2, float& d3,
    uint32_t a0, uint32_t a1, uint32_t a2, uint32_t a3,
    uint32_t b0, uint32_t b1)
{
    asm volatile(
        "mma.sync.aligned.m16n8k16.row.col.f32.f16.f16.f32 "
        "{%0,%1,%2,%3}, {%4,%5,%6,%7}, {%8,%9}, {%0,%1,%2,%3};"
        : "+f"(d0), "+f"(d1), "+f"(d2), "+f"(d3)
        : "r"(a0), "r"(a1), "r"(a2), "r"(a3), "r"(b0), "r"(b1));
}

__global__ void __launch_bounds__(128) gemm_h_kernel(const float* __restrict__ feat)
{
    int gw = (blockIdx.x * blockDim.x + threadIdx.x) >> 5;   // warp id
    if (gw >= N_NODES / 16) return;                          // 3125 warps exactly
    int lane = threadIdx.x & 31;
    int gp   = lane >> 2;
    int tg   = lane & 3;
    int r0   = gw * 16 + gp;                                 // rows r0, r0+8

    float acc[16][4];
#pragma unroll
    for (int nt = 0; nt < 16; nt++)
#pragma unroll
        for (int j = 0; j < 4; j++) acc[nt][j] = 0.f;

#pragma unroll
    for (int ks = 0; ks < 8; ks++) {
        int k0 = 16 * ks + 2 * tg;
        float2 f0 = *reinterpret_cast<const float2*>(feat + (r0    ) * D + k0    );
        float2 f1 = *reinterpret_cast<const float2*>(feat + (r0 + 8) * D + k0    );
        float2 f2 = *reinterpret_cast<const float2*>(feat + (r0    ) * D + k0 + 8);
        float2 f3 = *reinterpret_cast<const float2*>(feat + (r0 + 8) * D + k0 + 8);
        uint32_t a0 = pack_h2(f0.x, f0.y);
        uint32_t a1 = pack_h2(f1.x, f1.y);
        uint32_t a2 = pack_h2(f2.x, f2.y);
        uint32_t a3 = pack_h2(f3.x, f3.y);
#pragma unroll
        for (int np = 0; np < 8; np++) {
            uint4 b = g_wfrag[ks * 256 + np * 32 + lane];
            mma_f16(acc[2 * np][0], acc[2 * np][1], acc[2 * np][2], acc[2 * np][3],
                    a0, a1, a2, a3, b.x, b.y);
            mma_f16(acc[2 * np + 1][0], acc[2 * np + 1][1],
                    acc[2 * np + 1][2], acc[2 * np + 1][3],
                    a0, a1, a2, a3, b.z, b.w);
        }
    }

    // store h16: lane (gp,tg) holds cols 8nt+2tg,+1 for rows r0 and r0+8
#pragma unroll
    for (int nt = 0; nt < 16; nt++) {
        int c = nt * 8 + 2 * tg;
        *reinterpret_cast<uint32_t*>(g_h16 + (r0    ) * D + c) =
            pack_h2(acc[nt][0], acc[nt][1]);
        *reinterpret_cast<uint32_t*>(g_h16 + (r0 + 8) * D + c) =
            pack_h2(acc[nt][2], acc[nt][3]);
    }
}

// ---------------------------------------------------------------------------
// 4) gather: warp-per-node over h16, fp32 accum, + bias, relu, write out.
// ---------------------------------------------------------------------------
__device__ __forceinline__ void acc_add(float4& a, uint2 u) {
    __half2 h0 = *reinterpret_cast<__half2*>(&u.x);
    __half2 h1 = *reinterpret_cast<__half2*>(&u.y);
    float2 f0 = __half22float2(h0);
    float2 f1 = __half22float2(h1);
    a.x += f0.x; a.y += f0.y; a.z += f1.x; a.w += f1.y;
}

__global__ void __launch_bounds__(256) gather_kernel(
    const float* __restrict__ bias, float* __restrict__ out)
{
    int warp = (blockIdx.x * blockDim.x + threadIdx.x) >> 5;
    int lane = threadIdx.x & 31;
    if (warp >= N_NODES) return;

    const uint2* f = reinterpret_cast<const uint2*>(g_h16);   // 32 uint2/row

    int degf = g_cursor[warp];
    int deg  = min(degf, CAP);
    const int* bin = &g_bins[warp * CAP];

    float4 acc = make_float4(0.f, 0.f, 0.f, 0.f);

    int e = 0;
    for (; e + 8 <= deg; e += 8) {
        int s0 = bin[e];     int s1 = bin[e + 1];
        int s2 = bin[e + 2]; int s3 = bin[e + 3];
        int s4 = bin[e + 4]; int s5 = bin[e + 5];
        int s6 = bin[e + 6]; int s7 = bin[e + 7];
        uint2 u0 = f[s0 * 32 + lane];
        uint2 u1 = f[s1 * 32 + lane];
        uint2 u2 = f[s2 * 32 + lane];
        uint2 u3 = f[s3 * 32 + lane];
        uint2 u4 = f[s4 * 32 + lane];
        uint2 u5 = f[s5 * 32 + lane];
        uint2 u6 = f[s6 * 32 + lane];
        uint2 u7 = f[s7 * 32 + lane];
        acc_add(acc, u0); acc_add(acc, u1);
        acc_add(acc, u2); acc_add(acc, u3);
        acc_add(acc, u4); acc_add(acc, u5);
        acc_add(acc, u6); acc_add(acc, u7);
    }
    for (; e + 4 <= deg; e += 4) {
        int s0 = bin[e];     int s1 = bin[e + 1];
        int s2 = bin[e + 2]; int s3 = bin[e + 3];
        uint2 u0 = f[s0 * 32 + lane];
        uint2 u1 = f[s1 * 32 + lane];
        uint2 u2 = f[s2 * 32 + lane];
        uint2 u3 = f[s3 * 32 + lane];
        acc_add(acc, u0); acc_add(acc, u1);
        acc_add(acc, u2); acc_add(acc, u3);
    }
    for (; e < deg; e++) {
        uint2 u = f[bin[e] * 32 + lane];
        acc_add(acc, u);
    }

    if (degf > CAP) {                 // inline overflow fixup (expected never)
        int cnt = g_ovf_cnt;
        for (int j = 0; j < cnt; j++) {
            int2 sd = g_ovf[j];
            if (sd.y == warp) {
                uint2 u = f[sd.x * 32 + lane];
                acc_add(acc, u);
            }
        }
    }

    float4 bv = *reinterpret_cast<const float4*>(bias + lane * 4);
    float4 r;
    r.x = fmaxf(acc.x + bv.x, 0.f);
    r.y = fmaxf(acc.y + bv.y, 0.f);
    r.z = fmaxf(acc.z + bv.z, 0.f);
    r.w = fmaxf(acc.w + bv.w, 0.f);
    reinterpret_cast<float4*>(out)[warp * 32 + lane] = r;
}

// ---------------------------------------------------------------------------
extern "C" void kernel_launch(void* const* d_in, const int* in_sizes, int n_in,
                              void* d_out, int out_size)
{
    const float* feature = (const float*)d_in[0];   // [50000,128]
    const float* Wm      = (const float*)d_in[1];   // [128,128]
    const float* bias    = (const float*)d_in[2];   // [128]
    const int*   ei      = (const int*)  d_in[3];   // [2,800000]
    float*       out     = (float*)d_out;           // [50000,128]

    (void)in_sizes; (void)n_in; (void)out_size;

    prep_kernel<<<(N_NODES + 255) / 256, 256>>>(Wm);
    fill_kernel<<<(N_EDGES / 4 + 255) / 256, 256>>>(ei);
    {
        int warps = N_NODES / 16;                   // 3125
        int blocks = (warps * 32 + 127) / 128;      // 782
        gemm_h_kernel<<<blocks, 128>>>(feature);
    }
    {
        int total_threads = N_NODES * 32;
        gather_kernel<<<(total_threads + 255) / 256, 256>>>(bias, out);
    }
}